// round 2
// baseline (speedup 1.0000x reference)
#include <cuda_runtime.h>

#define NAG    12
#define NENV   4096
#define NNODE  (NENV*NAG)
#define TPB    384

// shared float offsets
#define OFF_WTA  0        // 32 k4-blocks x 260 = 8320 (We1 node part / Wh1, transposed)
#define OFF_WTB  8320     // 16 k4-blocks x 260 = 4160 (Wemb / We2 / Wh2, transposed)
#define OFF_H    12480    // 12x64
#define OFF_P2   13248    // 12x32 float2 (P2 pairs) ; reused as t1 [12][64]
#define OFF_AGG  14016    // 12x64
#define OFF_XS   14784    // 12x12
#define OFF_RAD  14928    // 132x4
#define OFF_MS   15456    // 12 warps x 256
#define SMEM_FLOATS 18528
#define SMEM_BYTES  (SMEM_FLOATS*4)

__device__ __forceinline__ float siluf(float v) { return v / (1.0f + __expf(-v)); }

// stage K x 64 row-major weight matrix into transposed k-blocked layout:
// dst[(k>>2)*260 + c*4 + (k&3)] = src[k*64 + c]
template<int K, int LOGK>
__device__ __forceinline__ void stageT(float* dst, const float* src, int tid) {
    const float4* s4 = (const float4*)src;
    for (int f = tid; f < K * 16; f += TPB) {
        int k  = f & (K - 1);
        int c4 = f >> LOGK;
        float4 v = __ldg(&s4[(k << 4) + c4]);
        int d = (k >> 2) * 260 + (c4 << 4) + (k & 3);
        dst[d]      = v.x;
        dst[d + 4]  = v.y;
        dst[d + 8]  = v.z;
        dst[d + 12] = v.w;
    }
}

extern "C" __global__ void __launch_bounds__(TPB, 2)
egnn_kernel(const float* __restrict__ h0,   const float* __restrict__ x0,
            const float* __restrict__ Wemb, const float* __restrict__ bemb,
            const float* __restrict__ We1,  const float* __restrict__ be1,
            const float* __restrict__ We2,  const float* __restrict__ be2,
            const float* __restrict__ Wx,   const float* __restrict__ bx,
            const float* __restrict__ Wh1,  const float* __restrict__ bh1,
            const float* __restrict__ Wh2,  const float* __restrict__ bh2,
            const float* __restrict__ w_act,const float* __restrict__ log_std,
            float* __restrict__ out)
{
    extern __shared__ float sm[];
    float* WTA = sm + OFF_WTA;
    float* WTB = sm + OFF_WTB;
    float* hs  = sm + OFF_H;
    float* P2p = sm + OFF_P2;   // float2[12][32]
    float* t1s = sm + OFF_P2;   // [12][64] (phase-disjoint reuse)
    float* agg = sm + OFF_AGG;
    float* xs  = sm + OFF_XS;
    float* rad = sm + OFF_RAD;
    float* ms  = sm + OFF_MS;

    const int tid  = threadIdx.x;
    const int w    = tid >> 5;
    const int lane = tid & 31;
    const int env  = blockIdx.x;
    const int base = env * NAG;

    // ---------- phase 0: stage x + W_embed^T ; embed h ----------
    if (tid < NAG * NAG) xs[tid] = x0[base * 12 + tid];
    stageT<32, 5>(WTB, Wemb, tid);
    __syncthreads();
    {   // warp w -> node w : h = h0 @ Wemb + bemb
        const int n = w;
        float a0 = __ldg(&bemb[lane]);
        float a1 = __ldg(&bemb[lane + 32]);
        const float4* h0p = (const float4*)h0 + (base + n) * 8;
        #pragma unroll
        for (int k4 = 0; k4 < 8; k4++) {
            float4 h4 = __ldg(&h0p[k4]);
            float4 w0 = *(const float4*)&WTB[k4*260 + lane*4];
            float4 w1 = *(const float4*)&WTB[k4*260 + (lane+32)*4];
            a0 += h4.x*w0.x + h4.y*w0.y + h4.z*w0.z + h4.w*w0.w;
            a1 += h4.x*w1.x + h4.y*w1.y + h4.z*w1.z + h4.w*w1.w;
        }
        hs[n*64 + lane]      = a0;
        hs[n*64 + lane + 32] = a1;
    }

    // ---------- layers ----------
    for (int l = 0; l < 2; l++) {
        __syncthreads();
        stageT<128, 7>(WTA, We1 + l * 8448, tid);   // rows 0..127 (hi|hj part)
        stageT<64, 6>(WTB, We2 + l * 4096, tid);
        // radial per edge
        if (tid < 132) {
            int e = tid, i = e / 11, tt = e - 11 * i, j = tt + (tt >= i);
            float s0 = 0.f, s1 = 0.f, s2 = 0.f, s3 = 0.f;
            #pragma unroll
            for (int d = 0; d < 3; d++) {
                float d0 = xs[i*12 + d*4 + 0] - xs[j*12 + d*4 + 0]; s0 += d0*d0;
                float d1 = xs[i*12 + d*4 + 1] - xs[j*12 + d*4 + 1]; s1 += d1*d1;
                float d2 = xs[i*12 + d*4 + 2] - xs[j*12 + d*4 + 2]; s2 += d2*d2;
                float d3 = xs[i*12 + d*4 + 3] - xs[j*12 + d*4 + 3]; s3 += d3*d3;
            }
            ((float4*)rad)[e] = make_float4(s0, s1, s2, s3);
        }
        __syncthreads();

        // ---- P-phase: P1 (kept in regs), P2 -> float2 pairs in smem ----
        float Pi0, Pi32;
        {
            const int n = w;
            float a0 = __ldg(&be1[l*64 + lane]);
            float a1 = __ldg(&be1[l*64 + lane + 32]);
            float a2 = 0.f, a3 = 0.f;
            #pragma unroll
            for (int k4 = 0; k4 < 16; k4++) {
                float4 h4 = *(const float4*)&hs[n*64 + k4*4];
                float4 wa = *(const float4*)&WTA[k4*260 + lane*4];
                float4 wb = *(const float4*)&WTA[k4*260 + (lane+32)*4];
                float4 wc2 = *(const float4*)&WTA[(16+k4)*260 + lane*4];
                float4 wd = *(const float4*)&WTA[(16+k4)*260 + (lane+32)*4];
                a0 += h4.x*wa.x + h4.y*wa.y + h4.z*wa.z + h4.w*wa.w;
                a1 += h4.x*wb.x + h4.y*wb.y + h4.z*wb.z + h4.w*wb.w;
                a2 += h4.x*wc2.x + h4.y*wc2.y + h4.z*wc2.z + h4.w*wc2.w;
                a3 += h4.x*wd.x + h4.y*wd.y + h4.z*wd.z + h4.w*wd.w;
            }
            Pi0 = a0; Pi32 = a1;
            ((float2*)P2p)[n*32 + lane] = make_float2(a2, a3);
        }
        __syncthreads();

        // ---- edge phase: warp w owns node i=w ----
        {
            const int i = w;
            const float4 wxA = __ldg((const float4*)&Wx[l*256 + lane*4]);
            const float4 wxB = __ldg((const float4*)&Wx[l*256 + (lane+32)*4]);
            const float4 bxv = __ldg((const float4*)&bx[l*4]);
            const float be2a = __ldg(&be2[l*64 + lane]);
            const float be2b = __ldg(&be2[l*64 + lane + 32]);
            float wrA[4], wrB[4];
            #pragma unroll
            for (int v = 0; v < 4; v++) {
                wrA[v] = __ldg(&We1[l*8448 + (128+v)*64 + lane]);
                wrB[v] = __ldg(&We1[l*8448 + (128+v)*64 + lane + 32]);
            }
            const float xi = (lane < 12) ? xs[i*12 + lane] : 0.f;
            float aggA = 0.f, aggB = 0.f, dxr = 0.f;
            float* msw = ms + w * 256;

            for (int g0 = 0; g0 < 11; g0 += 4) {
                const int cnt = (11 - g0 < 4) ? (11 - g0) : 4;
                // MLP1
                #pragma unroll
                for (int gg = 0; gg < 4; gg++) if (gg < cnt) {
                    int tt = g0 + gg, j = tt + (tt >= i);
                    float2 pj = ((const float2*)P2p)[j*32 + lane];
                    float4 rv = ((const float4*)rad)[i*11 + tt];
                    float aA = Pi0  + pj.x
                             + rv.x*wrA[0] + rv.y*wrA[1] + rv.z*wrA[2] + rv.w*wrA[3];
                    float aB = Pi32 + pj.y
                             + rv.x*wrB[0] + rv.y*wrB[1] + rv.z*wrB[2] + rv.w*wrB[3];
                    msw[gg*64 + lane]      = siluf(aA);
                    msw[gg*64 + lane + 32] = siluf(aB);
                }
                __syncwarp();
                // MLP2: vectorized transposed weights
                float acc0[4] = {be2a, be2a, be2a, be2a};
                float acc1[4] = {be2b, be2b, be2b, be2b};
                #pragma unroll
                for (int k4 = 0; k4 < 16; k4++) {
                    float4 w0 = *(const float4*)&WTB[k4*260 + lane*4];
                    float4 w1 = *(const float4*)&WTB[k4*260 + (lane+32)*4];
                    #pragma unroll
                    for (int gg = 0; gg < 4; gg++) if (gg < cnt) {
                        float4 aq = *(const float4*)&msw[gg*64 + k4*4];
                        acc0[gg] += aq.x*w0.x + aq.y*w0.y + aq.z*w0.z + aq.w*w0.w;
                        acc1[gg] += aq.x*w1.x + aq.y*w1.y + aq.z*w1.z + aq.w*w1.w;
                    }
                }
                // epilogue
                #pragma unroll
                for (int gg = 0; gg < 4; gg++) if (gg < cnt) {
                    float m0  = siluf(acc0[gg]);
                    float m1v = siluf(acc1[gg]);
                    aggA += m0; aggB += m1v;
                    float p0 = m0*wxA.x + m1v*wxB.x;
                    float p1 = m0*wxA.y + m1v*wxB.y;
                    float p2 = m0*wxA.z + m1v*wxB.z;
                    float p3 = m0*wxA.w + m1v*wxB.w;
                    #pragma unroll
                    for (int off = 16; off; off >>= 1) {
                        p0 += __shfl_xor_sync(0xffffffffu, p0, off);
                        p1 += __shfl_xor_sync(0xffffffffu, p1, off);
                        p2 += __shfl_xor_sync(0xffffffffu, p2, off);
                        p3 += __shfl_xor_sync(0xffffffffu, p3, off);
                    }
                    if (lane < 12) {
                        int tt = g0 + gg, j = tt + (tt >= i);
                        int v = lane & 3;
                        float wc = (v == 0) ? (p0 + bxv.x) :
                                   (v == 1) ? (p1 + bxv.y) :
                                   (v == 2) ? (p2 + bxv.z) : (p3 + bxv.w);
                        dxr += (xi - xs[j*12 + lane]) * wc;
                    }
                }
                __syncwarp();
            }
            agg[i*64 + lane]      = aggA;
            agg[i*64 + lane + 32] = aggB;
            if (lane < 12) xs[i*12 + lane] = xi + dxr * (1.0f / 11.0f);
        }
        __syncthreads();
        stageT<128, 7>(WTA, Wh1 + l * 8192, tid);
        stageT<64, 6>(WTB, Wh2 + l * 4096, tid);
        __syncthreads();

        // t1 = silu([h, agg] @ Wh1 + bh1)
        {
            const int n = w;
            float a0 = __ldg(&bh1[l*64 + lane]);
            float a1 = __ldg(&bh1[l*64 + lane + 32]);
            #pragma unroll
            for (int k4 = 0; k4 < 16; k4++) {
                float4 h4 = *(const float4*)&hs[n*64 + k4*4];
                float4 w0 = *(const float4*)&WTA[k4*260 + lane*4];
                float4 w1 = *(const float4*)&WTA[k4*260 + (lane+32)*4];
                a0 += h4.x*w0.x + h4.y*w0.y + h4.z*w0.z + h4.w*w0.w;
                a1 += h4.x*w1.x + h4.y*w1.y + h4.z*w1.z + h4.w*w1.w;
            }
            #pragma unroll
            for (int k4 = 0; k4 < 16; k4++) {
                float4 g4 = *(const float4*)&agg[n*64 + k4*4];
                float4 w0 = *(const float4*)&WTA[(16+k4)*260 + lane*4];
                float4 w1 = *(const float4*)&WTA[(16+k4)*260 + (lane+32)*4];
                a0 += g4.x*w0.x + g4.y*w0.y + g4.z*w0.z + g4.w*w0.w;
                a1 += g4.x*w1.x + g4.y*w1.y + g4.z*w1.z + g4.w*w1.w;
            }
            float s0 = siluf(a0), s1 = siluf(a1);
            __syncthreads();              // protect t1s/P2p aliasing
            t1s[n*64 + lane]      = s0;
            t1s[n*64 + lane + 32] = s1;
        }
        __syncthreads();
        // h += t1 @ Wh2 + bh2
        {
            const int n = w;
            float a0 = __ldg(&bh2[l*64 + lane]);
            float a1 = __ldg(&bh2[l*64 + lane + 32]);
            #pragma unroll
            for (int k4 = 0; k4 < 16; k4++) {
                float4 t4 = *(const float4*)&t1s[n*64 + k4*4];
                float4 w0 = *(const float4*)&WTB[k4*260 + lane*4];
                float4 w1 = *(const float4*)&WTB[k4*260 + (lane+32)*4];
                a0 += t4.x*w0.x + t4.y*w0.y + t4.z*w0.z + t4.w*w0.w;
                a1 += t4.x*w1.x + t4.y*w1.y + t4.z*w1.z + t4.w*w1.w;
            }
            hs[n*64 + lane]      += a0;
            hs[n*64 + lane + 32] += a1;
        }
    }
    __syncthreads();
    // ---------- output ----------
    if (tid < NAG * 3) {
        int a = tid / 3, d = tid - 3 * a;
        float mu = 0.f;
        #pragma unroll
        for (int v = 0; v < 4; v++) mu += xs[a*12 + d*4 + v] * __ldg(&w_act[v]);
        out[(base + a) * 3 + d] = mu;
        out[NNODE * 3 + (base + a) * 3 + d] =
            -__ldg(&log_std[d]) - 0.91893853320467274178f;
    }
}

extern "C" void kernel_launch(void* const* d_in, const int* in_sizes, int n_in,
                              void* d_out, int out_size)
{
    (void)in_sizes; (void)n_in; (void)out_size;
    cudaFuncSetAttribute(egnn_kernel,
                         cudaFuncAttributeMaxDynamicSharedMemorySize, SMEM_BYTES);
    egnn_kernel<<<NENV, TPB, SMEM_BYTES>>>(
        (const float*)d_in[0],  (const float*)d_in[1],
        (const float*)d_in[2],  (const float*)d_in[3],
        (const float*)d_in[4],  (const float*)d_in[5],
        (const float*)d_in[6],  (const float*)d_in[7],
        (const float*)d_in[8],  (const float*)d_in[9],
        (const float*)d_in[10], (const float*)d_in[11],
        (const float*)d_in[12], (const float*)d_in[13],
        (const float*)d_in[14], (const float*)d_in[15],
        (float*)d_out);
}

// round 3
// speedup vs baseline: 1.2898x; 1.2898x over previous
#include <cuda_runtime.h>

#define NAG    12
#define NENV   4096
#define NNODE  (NENV*NAG)
#define TPB    192
#define NW     6

// shared float offsets
#define OFF_WA   0        // 8192 (We1[0:128] / Wh1)
#define OFF_WB   8192     // 4096 (Wemb / We2 / Wh2)
#define OFF_H    12288    // 12x64
#define OFF_P2   13056    // 12x32 float2 (P2) ; reused as t1 [12][64]
#define OFF_AGG  13824    // 12x64
#define OFF_XS0  14592    // 144
#define OFF_XS1  14736    // 144
#define OFF_RAD  14880    // 132x4
#define OFF_H0S  15408    // 12x32
#define OFF_MS   15792    // 6 warps x 512
#define SMEM_FLOATS 18864
#define SMEM_BYTES  (SMEM_FLOATS*4)

__device__ __forceinline__ float siluf(float v) { return v / (1.0f + __expf(-v)); }

extern "C" __global__ void __launch_bounds__(TPB, 3)
egnn_kernel(const float* __restrict__ h0,   const float* __restrict__ x0,
            const float* __restrict__ Wemb, const float* __restrict__ bemb,
            const float* __restrict__ We1,  const float* __restrict__ be1,
            const float* __restrict__ We2,  const float* __restrict__ be2,
            const float* __restrict__ Wx,   const float* __restrict__ bx,
            const float* __restrict__ Wh1,  const float* __restrict__ bh1,
            const float* __restrict__ Wh2,  const float* __restrict__ bh2,
            const float* __restrict__ w_act,const float* __restrict__ log_std,
            float* __restrict__ out)
{
    extern __shared__ float sm[];
    float* WA  = sm + OFF_WA;
    float* WB  = sm + OFF_WB;
    float* hs  = sm + OFF_H;
    float* P2p = sm + OFF_P2;   // float2[12][32]
    float* t1s = sm + OFF_P2;   // [12][64] phase-disjoint reuse
    float* agg = sm + OFF_AGG;
    float* xs0 = sm + OFF_XS0;
    float* xs1 = sm + OFF_XS1;
    float* rad = sm + OFF_RAD;
    float* h0s = sm + OFF_H0S;
    float* ms  = sm + OFF_MS;

    const int tid  = threadIdx.x;
    const int w    = tid >> 5;
    const int lane = tid & 31;
    const int env  = blockIdx.x;
    const int base = env * NAG;
    const int iA = 2 * w, iB = 2 * w + 1;

    // ---------- phase 0: stage x, h0, W_embed ; embed ----------
    if (tid < NAG * NAG) xs0[tid] = x0[base * 12 + tid];
    for (int t = tid; t < NAG * 32; t += TPB) h0s[t] = __ldg(&h0[base * 32 + t]);
    {
        float4* q = (float4*)WB;
        const float4* g = (const float4*)Wemb;
        for (int i = tid; i < 512; i += TPB) q[i] = __ldg(&g[i]);
    }
    __syncthreads();
    {   // h = h0 @ Wemb + bemb   (2 nodes per warp)
        float a0A = __ldg(&bemb[lane]),      a1A = __ldg(&bemb[lane + 32]);
        float a0B = a0A, a1B = a1A;
        #pragma unroll
        for (int k = 0; k < 32; k++) {
            float w0 = WB[k*64 + lane], w1 = WB[k*64 + lane + 32];
            float hA = h0s[iA*32 + k],  hB = h0s[iB*32 + k];
            a0A += hA*w0; a1A += hA*w1;
            a0B += hB*w0; a1B += hB*w1;
        }
        hs[iA*64 + lane] = a0A; hs[iA*64 + lane + 32] = a1A;
        hs[iB*64 + lane] = a0B; hs[iB*64 + lane + 32] = a1B;
    }

    // ---------- layers ----------
    for (int l = 0; l < 2; l++) {
        __syncthreads();
        float* xsr = (l == 0) ? xs0 : xs1;   // read (old x)
        float* xsw = (l == 0) ? xs1 : xs0;   // write (new x)
        {   // stage We1 rows 0..127 -> WA, We2 -> WB
            float4* q = (float4*)WA;
            const float4* g = (const float4*)(We1 + l * 8448);
            for (int i = tid; i < 2048; i += TPB) q[i] = __ldg(&g[i]);
            float4* q2 = (float4*)WB;
            const float4* g2 = (const float4*)(We2 + l * 4096);
            for (int i = tid; i < 1024; i += TPB) q2[i] = __ldg(&g2[i]);
        }
        if (tid < 132) {   // radial per edge
            int e = tid, i = e / 11, tt = e - 11 * i, j = tt + (tt >= i);
            float s0 = 0.f, s1 = 0.f, s2 = 0.f, s3 = 0.f;
            #pragma unroll
            for (int d = 0; d < 3; d++) {
                float d0 = xsr[i*12 + d*4 + 0] - xsr[j*12 + d*4 + 0]; s0 += d0*d0;
                float d1 = xsr[i*12 + d*4 + 1] - xsr[j*12 + d*4 + 1]; s1 += d1*d1;
                float d2 = xsr[i*12 + d*4 + 2] - xsr[j*12 + d*4 + 2]; s2 += d2*d2;
                float d3 = xsr[i*12 + d*4 + 3] - xsr[j*12 + d*4 + 3]; s3 += d3*d3;
            }
            ((float4*)rad)[e] = make_float4(s0, s1, s2, s3);
        }
        __syncthreads();

        // ---- P-phase (2 nodes per warp): P1 in regs, P2 -> smem ----
        float PiA0, PiA1, PiB0, PiB1;
        {
            float b0 = __ldg(&be1[l*64 + lane]), b1 = __ldg(&be1[l*64 + lane + 32]);
            float a0A = b0, a1A = b1, a2A = 0.f, a3A = 0.f;
            float a0B = b0, a1B = b1, a2B = 0.f, a3B = 0.f;
            #pragma unroll
            for (int k = 0; k < 64; k++) {
                float w0 = WA[k*64 + lane],        w1 = WA[k*64 + lane + 32];
                float w2 = WA[(64+k)*64 + lane],   w3 = WA[(64+k)*64 + lane + 32];
                float hA = hs[iA*64 + k], hB = hs[iB*64 + k];
                a0A += hA*w0; a1A += hA*w1; a2A += hA*w2; a3A += hA*w3;
                a0B += hB*w0; a1B += hB*w1; a2B += hB*w2; a3B += hB*w3;
            }
            PiA0 = a0A; PiA1 = a1A; PiB0 = a0B; PiB1 = a1B;
            ((float2*)P2p)[iA*32 + lane] = make_float2(a2A, a3A);
            ((float2*)P2p)[iB*32 + lane] = make_float2(a2B, a3B);
        }
        __syncthreads();

        // ---- edge phase: warp w owns nodes iA, iB (22 edges) ----
        {
            const float4 wxA = __ldg((const float4*)&Wx[l*256 + lane*4]);
            const float4 wxB = __ldg((const float4*)&Wx[l*256 + (lane+32)*4]);
            const float4 bxv = __ldg((const float4*)&bx[l*4]);
            const float be2a = __ldg(&be2[l*64 + lane]);
            const float be2b = __ldg(&be2[l*64 + lane + 32]);
            float wrA[4], wrB[4];
            #pragma unroll
            for (int v = 0; v < 4; v++) {
                wrA[v] = __ldg(&We1[l*8448 + (128+v)*64 + lane]);
                wrB[v] = __ldg(&We1[l*8448 + (128+v)*64 + lane + 32]);
            }
            const float xiA = (lane < 12) ? xsr[iA*12 + lane] : 0.f;
            const float xiB = (lane < 12) ? xsr[iB*12 + lane] : 0.f;
            float agA0 = 0.f, agB0 = 0.f, agA1 = 0.f, agB1 = 0.f;
            float dx0 = 0.f, dx1 = 0.f;
            float* msw = ms + w * 512;

            #pragma unroll
            for (int g0 = 0; g0 < 22; g0 += 8) {
                const int cnt = (22 - g0 < 8) ? (22 - g0) : 8;
                // MLP1
                #pragma unroll
                for (int gg = 0; gg < 8; gg++) if (gg < cnt) {
                    const int t = g0 + gg;
                    const int i  = (t < 11) ? iA : iB;
                    const int tt = (t < 11) ? t : (t - 11);
                    const int j  = tt + (tt >= i);
                    float2 pj = ((const float2*)P2p)[j*32 + lane];
                    float4 rv = ((const float4*)rad)[i*11 + tt];
                    float P1a = (t < 11) ? PiA0 : PiB0;
                    float P1b = (t < 11) ? PiA1 : PiB1;
                    float aA = P1a + pj.x
                             + rv.x*wrA[0] + rv.y*wrA[1] + rv.z*wrA[2] + rv.w*wrA[3];
                    float aB = P1b + pj.y
                             + rv.x*wrB[0] + rv.y*wrB[1] + rv.z*wrB[2] + rv.w*wrB[3];
                    msw[gg*64 + lane]      = siluf(aA);
                    msw[gg*64 + lane + 32] = siluf(aB);
                }
                __syncwarp();
                // MLP2: weights read once per k4 for up to 8 edges
                float acc0[8], acc1[8];
                #pragma unroll
                for (int gg = 0; gg < 8; gg++) { acc0[gg] = be2a; acc1[gg] = be2b; }
                #pragma unroll
                for (int k4 = 0; k4 < 16; k4++) {
                    float w00 = WB[(4*k4+0)*64 + lane];
                    float w01 = WB[(4*k4+1)*64 + lane];
                    float w02 = WB[(4*k4+2)*64 + lane];
                    float w03 = WB[(4*k4+3)*64 + lane];
                    float w10 = WB[(4*k4+0)*64 + lane + 32];
                    float w11 = WB[(4*k4+1)*64 + lane + 32];
                    float w12 = WB[(4*k4+2)*64 + lane + 32];
                    float w13 = WB[(4*k4+3)*64 + lane + 32];
                    #pragma unroll
                    for (int gg = 0; gg < 8; gg++) if (gg < cnt) {
                        float4 aq = *(const float4*)&msw[gg*64 + k4*4];
                        acc0[gg] += aq.x*w00 + aq.y*w01 + aq.z*w02 + aq.w*w03;
                        acc1[gg] += aq.x*w10 + aq.y*w11 + aq.z*w12 + aq.w*w13;
                    }
                }
                // epilogue
                #pragma unroll
                for (int gg = 0; gg < 8; gg++) if (gg < cnt) {
                    const int t = g0 + gg;
                    const int i  = (t < 11) ? iA : iB;
                    const int tt = (t < 11) ? t : (t - 11);
                    const int j  = tt + (tt >= i);
                    float m0  = siluf(acc0[gg]);
                    float m1v = siluf(acc1[gg]);
                    if (t < 11) { agA0 += m0; agB0 += m1v; }
                    else        { agA1 += m0; agB1 += m1v; }
                    float p0 = m0*wxA.x + m1v*wxB.x;
                    float p1 = m0*wxA.y + m1v*wxB.y;
                    float p2 = m0*wxA.z + m1v*wxB.z;
                    float p3 = m0*wxA.w + m1v*wxB.w;
                    #pragma unroll
                    for (int off = 16; off; off >>= 1) {
                        p0 += __shfl_xor_sync(0xffffffffu, p0, off);
                        p1 += __shfl_xor_sync(0xffffffffu, p1, off);
                        p2 += __shfl_xor_sync(0xffffffffu, p2, off);
                        p3 += __shfl_xor_sync(0xffffffffu, p3, off);
                    }
                    if (lane < 12) {
                        int v = lane & 3;
                        float wc = (v == 0) ? (p0 + bxv.x) :
                                   (v == 1) ? (p1 + bxv.y) :
                                   (v == 2) ? (p2 + bxv.z) : (p3 + bxv.w);
                        float xi = (t < 11) ? xiA : xiB;
                        float d  = (xi - xsr[j*12 + lane]) * wc;
                        if (t < 11) dx0 += d; else dx1 += d;
                    }
                }
                __syncwarp();
            }
            agg[iA*64 + lane]      = agA0;
            agg[iA*64 + lane + 32] = agB0;
            agg[iB*64 + lane]      = agA1;
            agg[iB*64 + lane + 32] = agB1;
            if (lane < 12) {
                xsw[iA*12 + lane] = xiA + dx0 * (1.0f / 11.0f);
                xsw[iB*12 + lane] = xiB + dx1 * (1.0f / 11.0f);
            }
        }
        __syncthreads();
        {   // stage Wh1 -> WA, Wh2 -> WB
            float4* q = (float4*)WA;
            const float4* g = (const float4*)(Wh1 + l * 8192);
            for (int i = tid; i < 2048; i += TPB) q[i] = __ldg(&g[i]);
            float4* q2 = (float4*)WB;
            const float4* g2 = (const float4*)(Wh2 + l * 4096);
            for (int i = tid; i < 1024; i += TPB) q2[i] = __ldg(&g2[i]);
        }
        __syncthreads();

        // t1 = silu([h, agg] @ Wh1 + bh1)  (2 nodes per warp)
        {
            float b0 = __ldg(&bh1[l*64 + lane]), b1 = __ldg(&bh1[l*64 + lane + 32]);
            float a0A = b0, a1A = b1, a0B = b0, a1B = b1;
            #pragma unroll
            for (int k = 0; k < 64; k++) {
                float w0 = WA[k*64 + lane], w1 = WA[k*64 + lane + 32];
                float hA = hs[iA*64 + k],   hB = hs[iB*64 + k];
                a0A += hA*w0; a1A += hA*w1;
                a0B += hB*w0; a1B += hB*w1;
            }
            #pragma unroll
            for (int k = 0; k < 64; k++) {
                float w0 = WA[(64+k)*64 + lane], w1 = WA[(64+k)*64 + lane + 32];
                float gA = agg[iA*64 + k],       gB = agg[iB*64 + k];
                a0A += gA*w0; a1A += gA*w1;
                a0B += gB*w0; a1B += gB*w1;
            }
            float s0A = siluf(a0A), s1A = siluf(a1A);
            float s0B = siluf(a0B), s1B = siluf(a1B);
            __syncthreads();   // P2p (aliased by t1s) fully consumed before overwrite
            t1s[iA*64 + lane] = s0A; t1s[iA*64 + lane + 32] = s1A;
            t1s[iB*64 + lane] = s0B; t1s[iB*64 + lane + 32] = s1B;
        }
        __syncthreads();
        // h += t1 @ Wh2 + bh2
        {
            float b0 = __ldg(&bh2[l*64 + lane]), b1 = __ldg(&bh2[l*64 + lane + 32]);
            float a0A = b0, a1A = b1, a0B = b0, a1B = b1;
            #pragma unroll
            for (int k = 0; k < 64; k++) {
                float w0 = WB[k*64 + lane], w1 = WB[k*64 + lane + 32];
                float tA = t1s[iA*64 + k],  tB = t1s[iB*64 + k];
                a0A += tA*w0; a1A += tA*w1;
                a0B += tB*w0; a1B += tB*w1;
            }
            hs[iA*64 + lane]      += a0A;
            hs[iA*64 + lane + 32] += a1A;
            hs[iB*64 + lane]      += a0B;
            hs[iB*64 + lane + 32] += a1B;
        }
    }
    __syncthreads();
    // ---------- output: mu = x . w_act (final x in xs0) ----------
    if (tid < NAG * 3) {
        int a = tid / 3, d = tid - 3 * a;
        float mu = 0.f;
        #pragma unroll
        for (int v = 0; v < 4; v++) mu += xs0[a*12 + d*4 + v] * __ldg(&w_act[v]);
        out[(base + a) * 3 + d] = mu;
        out[NNODE * 3 + (base + a) * 3 + d] =
            -__ldg(&log_std[d]) - 0.91893853320467274178f;
    }
}

extern "C" void kernel_launch(void* const* d_in, const int* in_sizes, int n_in,
                              void* d_out, int out_size)
{
    (void)in_sizes; (void)n_in; (void)out_size;
    cudaFuncSetAttribute(egnn_kernel,
                         cudaFuncAttributeMaxDynamicSharedMemorySize, SMEM_BYTES);
    egnn_kernel<<<NENV, TPB, SMEM_BYTES>>>(
        (const float*)d_in[0],  (const float*)d_in[1],
        (const float*)d_in[2],  (const float*)d_in[3],
        (const float*)d_in[4],  (const float*)d_in[5],
        (const float*)d_in[6],  (const float*)d_in[7],
        (const float*)d_in[8],  (const float*)d_in[9],
        (const float*)d_in[10], (const float*)d_in[11],
        (const float*)d_in[12], (const float*)d_in[13],
        (const float*)d_in[14], (const float*)d_in[15],
        (float*)d_out);
}